// round 16
// baseline (speedup 1.0000x reference)
#include <cuda_runtime.h>
#include <math.h>

// ---------------------------------------------------------------------------
// GlobalLocalAwareEncoder — truncated-dependency implementation.
// T1: dilated segments never cross 256-token boundaries.
// T2: only token 0 per batch feeds the output (fused tail).
// T3: layer-2 needs only a 128-token compact set per batch.
// GEMMs: cp.async 3-stage pipelined tf32 MMA (raw fp32 / implicit RZ).
// proj / Wo / FFN2 use BN=256 tiles and fuse the following LayerNorm into
// their epilogue (write raw + normalized) — no standalone LN launches.
// ---------------------------------------------------------------------------

#define BATCH   16
#define SEQ     256
#define TOK     (BATCH * SEQ)   // 4096
#define CTOK    (BATCH * 128)   // 2048 compact rows
#define DIM     256
#define HEADS   8
#define HDIM    32
#define FFN_DIM 1024
#define INDIM   512
#define NCTX    4095

__device__ float g_x  [TOK * DIM];
__device__ float g_h  [TOK * DIM];
__device__ float g_q  [TOK * DIM];
__device__ float g_k  [TOK * DIM];
__device__ float g_v  [TOK * DIM];
__device__ float g_acc[TOK * DIM];
__device__ float g_ffn[TOK * FFN_DIM];

__device__ __forceinline__ int cmap(int c) {
    return c < 64 ? c : (c < 96 ? 64 + 2 * (c - 64) : 128 + 4 * (c - 96));
}
__device__ __forceinline__ int cinv(int tok) {
    return tok < 64 ? tok : (tok < 128 ? 64 + ((tok - 64) >> 1)
                                       : 96 + ((tok - 128) >> 2));
}

__device__ __forceinline__ float gelu_tanh(float x) {
    float x3 = x * x * x;
    return 0.5f * x * (1.0f + tanhf(0.7978845608028654f * (x + 0.044715f * x3)));
}

__device__ __forceinline__ void mma_tf32(float* d, uint4 a, unsigned b0, unsigned b1) {
    asm volatile(
        "mma.sync.aligned.m16n8k8.row.col.f32.tf32.tf32.f32 "
        "{%0,%1,%2,%3}, {%4,%5,%6,%7}, {%8,%9}, {%0,%1,%2,%3};"
        : "+f"(d[0]), "+f"(d[1]), "+f"(d[2]), "+f"(d[3])
        : "r"(a.x), "r"(a.y), "r"(a.z), "r"(a.w), "r"(b0), "r"(b1));
}

__device__ __forceinline__ void cpa16(unsigned dst, const float* src) {
    asm volatile("cp.async.cg.shared.global [%0], [%1], 16;" :: "r"(dst), "l"(src));
}

__device__ __forceinline__ float wred_sum(float v) {
#pragma unroll
    for (int o = 16; o > 0; o >>= 1) v += __shfl_xor_sync(0xffffffffu, v, o);
    return v;
}

__device__ __forceinline__ float pe_val(int row, int col,
                                        const float* __restrict__ tpos,
                                        const float* __restrict__ cpos) {
    int b = row >> 8, s = row & 255;
    const float* pp = (s == 0) ? (tpos + (size_t)b * 2)
                               : (cpos + ((size_t)b * NCTX + (s - 1)) * 2);
    float pos = (col < 128) ? pp[0] : pp[1];
    int dd = col & 127;
    int i  = dd & 63;
    float omega = expf(-(float)i * (9.210340371976184f / 64.0f));
    float ang = pos * omega;
    return (dd < 64) ? sinf(ang) : cosf(ang);
}

// ---------------------------------------------------------------------------
// Pipelined tf32 GEMM with FUSED LayerNorm epilogue.
// BM in {16,32}, BN=256 (one CTA owns full rows), BK=16, 3-stage, 256 thr.
// GMODE: 0 plain A / 1 gather feats (full rows) / 2 gather compact (cmap).
// EPI:   5 v+bias+0.3*posenc / 6 v+res (res full, row cmap'd) / 3 v+bias+res.
// Epilogue: Craw[row] = v; rowwise LN -> Cnorm[row].
// ---------------------------------------------------------------------------
#define PBSL 4224   // 16*264 words per B stage
#define BSSTL 264

template<int EPI, int BM, int GMODE>
__global__ __launch_bounds__(256)
void gemm_pipe_ln(const float* __restrict__ A, const float* __restrict__ B,
                  const float* __restrict__ bias, const float* __restrict__ res,
                  const float* __restrict__ lnsc, const float* __restrict__ lnbi,
                  float* __restrict__ Craw, float* __restrict__ Cnorm, int K,
                  const float* __restrict__ tfeat, const float* __restrict__ cfeat,
                  const float* __restrict__ tpos,  const float* __restrict__ cpos)
{
    constexpr int PASL = BM * 20;
    constexpr int MF   = BM / 16;

    extern __shared__ float sm[];
    float* AsB = sm;
    float* BsB = sm + 3 * PASL;
    float* ro  = sm;                    // reused for LN (BM*264 words)

    const int t    = threadIdx.x;
    const int lane = t & 31;
    const int wrp  = t >> 5;            // 0..7 = n-slice
    const int gid  = lane >> 2;
    const int tig  = lane & 3;

    const int bm = blockIdx.y * BM;

    const float* aptr = nullptr;
    unsigned a_dst = 0;
    if (t < BM * 4) {
        int arow = t >> 2;
        int acq  = (t & 3) * 4;
        if (GMODE == 1) {
            int row = bm + arow;
            int bi = row >> 8, s = row & 255;
            const float* rp = (s == 0) ? (tfeat + (size_t)bi * INDIM)
                                       : (cfeat + ((size_t)bi * NCTX + (s - 1)) * INDIM);
            aptr = rp + acq;
        } else if (GMODE == 2) {
            int row = bm + arow;
            int bi = row >> 7;
            int tok = cmap(row & 127);
            aptr = A + (size_t)(bi * 256 + tok) * K + acq;
        } else {
            aptr = A + (size_t)(bm + arow) * K + acq;
        }
        a_dst = (unsigned)__cvta_generic_to_shared(AsB + arow * 20 + acq);
    }

    int b_kr[4], b_nq[4];
    unsigned b_dst[4];
#pragma unroll
    for (int i = 0; i < 4; i++) {
        int idx = t + 256 * i;
        b_kr[i] = idx >> 6;             // 0..15
        b_nq[i] = (idx & 63) * 4;       // 0..252
        b_dst[i] = (unsigned)__cvta_generic_to_shared(BsB + b_kr[i] * BSSTL + b_nq[i]);
    }

    const int nchunks = K >> 4;

    auto issue = [&](int c) {
        if (c < nchunks) {
            int st = c % 3;
            if (t < BM * 4) cpa16(a_dst + st * PASL * 4, aptr + c * 16);
#pragma unroll
            for (int i = 0; i < 4; i++) {
                const float* src = B + (size_t)(c * 16 + b_kr[i]) * 256 + b_nq[i];
                cpa16(b_dst[i] + st * PBSL * 4, src);
            }
        }
        asm volatile("cp.async.commit_group;");
    };

    float accd[MF][4][4];
#pragma unroll
    for (int mf = 0; mf < MF; mf++)
#pragma unroll
        for (int nf = 0; nf < 4; nf++)
#pragma unroll
            for (int r = 0; r < 4; r++) accd[mf][nf][r] = 0.f;

    issue(0);
    issue(1);

    for (int c = 0; c < nchunks; c++) {
        asm volatile("cp.async.wait_group 1;");
        __syncthreads();
        issue(c + 2);

        const int st = c % 3;
        const float* Asp = AsB + st * PASL;
        const float* Bsp = BsB + st * PBSL;
#pragma unroll
        for (int kf = 0; kf < 2; kf++) {
            uint4 afr[MF];
#pragma unroll
            for (int mf = 0; mf < MF; mf++) {
                int rb = mf * 16;
                afr[mf].x = __float_as_uint(Asp[(rb + gid)     * 20 + kf * 8 + tig]);
                afr[mf].y = __float_as_uint(Asp[(rb + 8 + gid) * 20 + kf * 8 + tig]);
                afr[mf].z = __float_as_uint(Asp[(rb + gid)     * 20 + kf * 8 + tig + 4]);
                afr[mf].w = __float_as_uint(Asp[(rb + 8 + gid) * 20 + kf * 8 + tig + 4]);
            }
#pragma unroll
            for (int nf = 0; nf < 4; nf++) {
                int cb = wrp * 32 + nf * 8 + gid;
                unsigned bb0 = __float_as_uint(Bsp[(kf * 8 + tig)     * BSSTL + cb]);
                unsigned bb1 = __float_as_uint(Bsp[(kf * 8 + tig + 4) * BSSTL + cb]);
#pragma unroll
                for (int mf = 0; mf < MF; mf++)
                    mma_tf32(accd[mf][nf], afr[mf], bb0, bb1);
            }
        }
    }

    // ---- epilogue: raw values -> Craw + smem, then LN -> Cnorm ----
    __syncthreads();    // last chunk's smem reads done; only empty cp.async
                        // groups remain pending -> safe to overlay ro

#pragma unroll
    for (int mf = 0; mf < MF; mf++) {
#pragma unroll
        for (int nf = 0; nf < 4; nf++) {
            int col = wrp * 32 + nf * 8 + 2 * tig;
#pragma unroll
            for (int half = 0; half < 2; half++) {
                int lr = mf * 16 + gid + half * 8;      // local row
                int r  = bm + lr;
                float v0 = accd[mf][nf][half * 2 + 0];
                float v1 = accd[mf][nf][half * 2 + 1];
                if (EPI == 5) {
                    v0 += bias[col]     + 0.3f * pe_val(r, col,     tpos, cpos);
                    v1 += bias[col + 1] + 0.3f * pe_val(r, col + 1, tpos, cpos);
                } else if (EPI == 6) {
                    int bi = r >> 7;
                    int tok = cmap(r & 127);
                    size_t ridx = (size_t)(bi * 256 + tok) * 256 + col;
                    v0 += res[ridx]; v1 += res[ridx + 1];
                } else if (EPI == 3) {
                    size_t ridx = (size_t)r * 256 + col;
                    v0 += bias[col] + res[ridx];
                    v1 += bias[col + 1] + res[ridx + 1];
                }
                *(float2*)&Craw[(size_t)r * 256 + col] = make_float2(v0, v1);
                ro[lr * BSSTL + col]     = v0;
                ro[lr * BSSTL + col + 1] = v1;
            }
        }
    }
    __syncthreads();

    // ---- rowwise LN (identical math to the old standalone ln_kernel) ----
    constexpr int RPW = BM / 8;         // rows per warp
#pragma unroll
    for (int i = 0; i < RPW; i++) {
        int lr = wrp * RPW + i;
        const float* rp = &ro[lr * BSSTL];
        float4 u0 = *(const float4*)&rp[lane * 4];
        float4 u1 = *(const float4*)&rp[128 + lane * 4];
        float va[8] = {u0.x, u0.y, u0.z, u0.w, u1.x, u1.y, u1.z, u1.w};

        float s = 0.f;
#pragma unroll
        for (int c2 = 0; c2 < 8; c2++) s += va[c2];
        s = wred_sum(s);
        float mu = s * (1.0f / 256.0f);

        float ss = 0.f;
#pragma unroll
        for (int c2 = 0; c2 < 8; c2++) { float d = va[c2] - mu; ss += d * d; }
        ss = wred_sum(ss);
        float inv = rsqrtf(ss * (1.0f / 256.0f) + 1e-5f);

        float ov[8];
#pragma unroll
        for (int c2 = 0; c2 < 8; c2++) {
            int d = (c2 < 4) ? (lane * 4 + c2) : (128 + lane * 4 + (c2 - 4));
            ov[c2] = (va[c2] - mu) * inv * lnsc[d] + lnbi[d];
        }
        float* op = Cnorm + (size_t)(bm + lr) * 256;
        *(float4*)&op[lane * 4]       = make_float4(ov[0], ov[1], ov[2], ov[3]);
        *(float4*)&op[128 + lane * 4] = make_float4(ov[4], ov[5], ov[6], ov[7]);
    }
}

// ---------------------------------------------------------------------------
// Pipelined tf32 GEMM, BM=64, BN=128, BK=32, 3-stage, 256 threads.
// EPI: 0 store / 2 gelu(v+bias). blockIdx.z selects B/C.
// ---------------------------------------------------------------------------
#define PAS  2304   // 64*36
#define PBS  4352   // 32*136
#define GP_SMEM (3 * (PAS + PBS) * 4)

template<int EPI>
__global__ __launch_bounds__(256)
void gemm_pipe(const float* __restrict__ A,
               const float* __restrict__ B0, const float* __restrict__ B1,
               const float* __restrict__ B2,
               const float* __restrict__ bias,
               float* __restrict__ C0, float* __restrict__ C1, float* __restrict__ C2,
               int N, int K)
{
    extern __shared__ float sm[];
    float* AsB = sm;
    float* BsB = sm + 3 * PAS;

    const int z = blockIdx.z;
    const float* B = (z == 0) ? B0 : (z == 1) ? B1 : B2;
    float*       C = (z == 0) ? C0 : (z == 1) ? C1 : C2;

    const int t    = threadIdx.x;
    const int lane = t & 31;
    const int warp = t >> 5;
    const int wm   = warp >> 2;
    const int wn   = warp & 3;
    const int gid  = lane >> 2;
    const int tig  = lane & 3;

    const int bm = blockIdx.y * 64;
    const int bn = blockIdx.x * 128;

    const float* aptr[2];
    unsigned a_dst[2];
#pragma unroll
    for (int i = 0; i < 2; i++) {
        int idx  = t + 256 * i;
        int arow = idx >> 3;
        int acq  = (idx & 7) * 4;
        aptr[i] = A + (size_t)(bm + arow) * K + acq;
        a_dst[i] = (unsigned)__cvta_generic_to_shared(AsB + arow * 36 + acq);
    }

    int b_kr[4], b_nq[4];
    unsigned b_dst[4];
#pragma unroll
    for (int i = 0; i < 4; i++) {
        int idx = t + 256 * i;
        b_kr[i] = idx >> 5;
        b_nq[i] = (idx & 31) * 4;
        b_dst[i] = (unsigned)__cvta_generic_to_shared(BsB + b_kr[i] * 136 + b_nq[i]);
    }

    const int nchunks = K >> 5;

    auto issue = [&](int c) {
        if (c < nchunks) {
            int st = c % 3;
            cpa16(a_dst[0] + st * PAS * 4, aptr[0] + c * 32);
            cpa16(a_dst[1] + st * PAS * 4, aptr[1] + c * 32);
#pragma unroll
            for (int i = 0; i < 4; i++) {
                const float* src = B + (size_t)(c * 32 + b_kr[i]) * N + bn + b_nq[i];
                cpa16(b_dst[i] + st * PBS * 4, src);
            }
        }
        asm volatile("cp.async.commit_group;");
    };

    float accd[2][4][4];
#pragma unroll
    for (int mf = 0; mf < 2; mf++)
#pragma unroll
        for (int nf = 0; nf < 4; nf++)
#pragma unroll
            for (int r = 0; r < 4; r++) accd[mf][nf][r] = 0.f;

    issue(0);
    issue(1);

    for (int c = 0; c < nchunks; c++) {
        asm volatile("cp.async.wait_group 1;");
        __syncthreads();
        issue(c + 2);

        const int st = c % 3;
        const float* Asp = AsB + st * PAS;
        const float* Bsp = BsB + st * PBS;
#pragma unroll
        for (int kf = 0; kf < 4; kf++) {
            uint4 afr[2];
#pragma unroll
            for (int mf = 0; mf < 2; mf++) {
                int rb = wm * 32 + mf * 16;
                afr[mf].x = __float_as_uint(Asp[(rb + gid)     * 36 + kf * 8 + tig]);
                afr[mf].y = __float_as_uint(Asp[(rb + 8 + gid) * 36 + kf * 8 + tig]);
                afr[mf].z = __float_as_uint(Asp[(rb + gid)     * 36 + kf * 8 + tig + 4]);
                afr[mf].w = __float_as_uint(Asp[(rb + 8 + gid) * 36 + kf * 8 + tig + 4]);
            }
#pragma unroll
            for (int nf = 0; nf < 4; nf++) {
                int cb = wn * 32 + nf * 8 + gid;
                unsigned bb0 = __float_as_uint(Bsp[(kf * 8 + tig)     * 136 + cb]);
                unsigned bb1 = __float_as_uint(Bsp[(kf * 8 + tig + 4) * 136 + cb]);
                mma_tf32(accd[0][nf], afr[0], bb0, bb1);
                mma_tf32(accd[1][nf], afr[1], bb0, bb1);
            }
        }
    }

#pragma unroll
    for (int mf = 0; mf < 2; mf++) {
#pragma unroll
        for (int nf = 0; nf < 4; nf++) {
            int row = bm + wm * 32 + mf * 16 + gid;
            int col = bn + wn * 32 + nf * 8 + 2 * tig;
#pragma unroll
            for (int half = 0; half < 2; half++) {
                int r = row + half * 8;
                float v0 = accd[mf][nf][half * 2 + 0];
                float v1 = accd[mf][nf][half * 2 + 1];
                size_t idx = (size_t)r * N + col;
                if (EPI == 2) {
                    v0 = gelu_tanh(v0 + bias[col]);
                    v1 = gelu_tanh(v1 + bias[col + 1]);
                }
                *(float2*)&C[idx] = make_float2(v0, v1);
            }
        }
    }
}

// ---------------------------------------------------------------------------
// Pipelined tf32 GEMM, BM=32, BN=128, BK=32, 3-stage, 128 threads (KV).
// ---------------------------------------------------------------------------
#define PAS32 1152   // 32*36
#define PBS32 4352   // 32*136
#define GP32_SMEM (3 * (PAS32 + PBS32) * 4)

__global__ __launch_bounds__(128)
void gemm_pipe32(const float* __restrict__ A,
                 const float* __restrict__ B0, const float* __restrict__ B1,
                 float* __restrict__ C0, float* __restrict__ C1,
                 int N, int K)
{
    extern __shared__ float sm[];
    float* AsB = sm;
    float* BsB = sm + 3 * PAS32;

    const int z = blockIdx.z;
    const float* B = (z == 0) ? B0 : B1;
    float*       C = (z == 0) ? C0 : C1;

    const int t    = threadIdx.x;
    const int lane = t & 31;
    const int wn   = t >> 5;
    const int gid  = lane >> 2;
    const int tig  = lane & 3;

    const int bm = blockIdx.y * 32;
    const int bn = blockIdx.x * 128;

    const float* aptr[2];
    unsigned a_dst[2];
#pragma unroll
    for (int i = 0; i < 2; i++) {
        int idx  = t + 128 * i;
        int arow = idx >> 3;
        int acq  = (idx & 7) * 4;
        aptr[i] = A + (size_t)(bm + arow) * K + acq;
        a_dst[i] = (unsigned)__cvta_generic_to_shared(AsB + arow * 36 + acq);
    }

    int b_kr[8], b_nq[8];
    unsigned b_dst[8];
#pragma unroll
    for (int i = 0; i < 8; i++) {
        int idx = t + 128 * i;
        b_kr[i] = idx >> 5;
        b_nq[i] = (idx & 31) * 4;
        b_dst[i] = (unsigned)__cvta_generic_to_shared(BsB + b_kr[i] * 136 + b_nq[i]);
    }

    const int nchunks = K >> 5;

    auto issue = [&](int c) {
        if (c < nchunks) {
            int st = c % 3;
            cpa16(a_dst[0] + st * PAS32 * 4, aptr[0] + c * 32);
            cpa16(a_dst[1] + st * PAS32 * 4, aptr[1] + c * 32);
#pragma unroll
            for (int i = 0; i < 8; i++) {
                const float* src = B + (size_t)(c * 32 + b_kr[i]) * N + bn + b_nq[i];
                cpa16(b_dst[i] + st * PBS32 * 4, src);
            }
        }
        asm volatile("cp.async.commit_group;");
    };

    float accd[2][4][4];
#pragma unroll
    for (int mf = 0; mf < 2; mf++)
#pragma unroll
        for (int nf = 0; nf < 4; nf++)
#pragma unroll
            for (int r = 0; r < 4; r++) accd[mf][nf][r] = 0.f;

    issue(0);
    issue(1);

    for (int c = 0; c < nchunks; c++) {
        asm volatile("cp.async.wait_group 1;");
        __syncthreads();
        issue(c + 2);

        const int st = c % 3;
        const float* Asp = AsB + st * PAS32;
        const float* Bsp = BsB + st * PBS32;
#pragma unroll
        for (int kf = 0; kf < 4; kf++) {
            uint4 afr[2];
#pragma unroll
            for (int mf = 0; mf < 2; mf++) {
                int rb = mf * 16;
                afr[mf].x = __float_as_uint(Asp[(rb + gid)     * 36 + kf * 8 + tig]);
                afr[mf].y = __float_as_uint(Asp[(rb + 8 + gid) * 36 + kf * 8 + tig]);
                afr[mf].z = __float_as_uint(Asp[(rb + gid)     * 36 + kf * 8 + tig + 4]);
                afr[mf].w = __float_as_uint(Asp[(rb + 8 + gid) * 36 + kf * 8 + tig + 4]);
            }
#pragma unroll
            for (int nf = 0; nf < 4; nf++) {
                int cb = wn * 32 + nf * 8 + gid;
                unsigned bb0 = __float_as_uint(Bsp[(kf * 8 + tig)     * 136 + cb]);
                unsigned bb1 = __float_as_uint(Bsp[(kf * 8 + tig + 4) * 136 + cb]);
                mma_tf32(accd[0][nf], afr[0], bb0, bb1);
                mma_tf32(accd[1][nf], afr[1], bb0, bb1);
            }
        }
    }

#pragma unroll
    for (int mf = 0; mf < 2; mf++) {
#pragma unroll
        for (int nf = 0; nf < 4; nf++) {
            int row = bm + mf * 16 + gid;
            int col = bn + wn * 32 + nf * 8 + 2 * tig;
#pragma unroll
            for (int half = 0; half < 2; half++) {
                int r = row + half * 8;
                float v0 = accd[mf][nf][half * 2 + 0];
                float v1 = accd[mf][nf][half * 2 + 1];
                *(float2*)&C[(size_t)r * N + col] = make_float2(v0, v1);
            }
        }
    }
}

// ---------------------------------------------------------------------------
// Layer-1 dilated attention on tf32 tensor cores (grid 896, 128 threads).
// ---------------------------------------------------------------------------
__global__ __launch_bounds__(128)
void attn_all_kernel(const float* __restrict__ q, const float* __restrict__ k,
                     const float* __restrict__ v, float* __restrict__ acc)
{
    __shared__ unsigned sh[64 * 36 * 2 + 64 * 40];
    unsigned* qs  = sh;
    unsigned* ks  = sh + 64 * 36;
    unsigned* vs  = sh + 64 * 72;
    unsigned* smP = sh;

    int bid = blockIdx.x;
    int r, w;
    if (bid < 512)      { w = 64;  r = 1; }
    else if (bid < 768) { bid -= 512; w = 128; r = 2; }
    else                { bid -= 768; w = 256; r = 4; }

    const int nseg = SEQ / w;
    const int h   = bid & 7;
    const int seg = (bid >> 3) % nseg;
    const int b   = bid / (8 * nseg);
    const int base = b * SEQ + seg * w;
    const int off  = h % r;
    const int t    = threadIdx.x;
    const int lane = t & 31;
    const int wrp  = t >> 5;
    const int gid  = lane >> 2;
    const int tig  = lane & 3;

#pragma unroll
    for (int i = 0; i < 4; i++) {
        int idx = t + 128 * i;
        int j  = idx >> 3;
        int dq = (idx & 7) * 4;
        int tok = base + off + r * j;
        size_t gi = (size_t)tok * DIM + h * HDIM + dq;
        cpa16((unsigned)__cvta_generic_to_shared(&qs[j * 36 + dq]), &q[gi]);
        cpa16((unsigned)__cvta_generic_to_shared(&ks[j * 36 + dq]), &k[gi]);
        cpa16((unsigned)__cvta_generic_to_shared(&vs[j * 40 + dq]), &v[gi]);
    }
    asm volatile("cp.async.commit_group;");
    asm volatile("cp.async.wait_group 0;");
    __syncthreads();

    const int rA = wrp * 16 + gid;
    const int rB = rA + 8;
    float sacc[8][4];
#pragma unroll
    for (int nf = 0; nf < 8; nf++)
#pragma unroll
        for (int c = 0; c < 4; c++) sacc[nf][c] = 0.f;

#pragma unroll
    for (int kc = 0; kc < 4; kc++) {
        uint4 afr;
        afr.x = qs[rA * 36 + kc * 8 + tig];
        afr.y = qs[rB * 36 + kc * 8 + tig];
        afr.z = qs[rA * 36 + kc * 8 + tig + 4];
        afr.w = qs[rB * 36 + kc * 8 + tig + 4];
#pragma unroll
        for (int nf = 0; nf < 8; nf++) {
            unsigned bb0 = ks[(nf * 8 + gid) * 36 + kc * 8 + tig];
            unsigned bb1 = ks[(nf * 8 + gid) * 36 + kc * 8 + tig + 4];
            mma_tf32(sacc[nf], afr, bb0, bb1);
        }
    }

    const float scl = 0.17677669529663687f;
    float mA = -1e30f, mB = -1e30f;
#pragma unroll
    for (int nf = 0; nf < 8; nf++) {
        sacc[nf][0] *= scl; sacc[nf][1] *= scl;
        sacc[nf][2] *= scl; sacc[nf][3] *= scl;
        mA = fmaxf(mA, fmaxf(sacc[nf][0], sacc[nf][1]));
        mB = fmaxf(mB, fmaxf(sacc[nf][2], sacc[nf][3]));
    }
#pragma unroll
    for (int o = 2; o > 0; o >>= 1) {
        mA = fmaxf(mA, __shfl_xor_sync(0xffffffffu, mA, o));
        mB = fmaxf(mB, __shfl_xor_sync(0xffffffffu, mB, o));
    }
    float sA = 0.f, sB = 0.f;
#pragma unroll
    for (int nf = 0; nf < 8; nf++) {
        sacc[nf][0] = __expf(sacc[nf][0] - mA); sA += sacc[nf][0];
        sacc[nf][1] = __expf(sacc[nf][1] - mA); sA += sacc[nf][1];
        sacc[nf][2] = __expf(sacc[nf][2] - mB); sB += sacc[nf][2];
        sacc[nf][3] = __expf(sacc[nf][3] - mB); sB += sacc[nf][3];
    }
#pragma unroll
    for (int o = 2; o > 0; o >>= 1) {
        sA += __shfl_xor_sync(0xffffffffu, sA, o);
        sB += __shfl_xor_sync(0xffffffffu, sB, o);
    }
    const float iA = 1.0f / sA, iB = 1.0f / sB;

    __syncthreads();

#pragma unroll
    for (int nf = 0; nf < 8; nf++) {
        int col = nf * 8 + 2 * tig;
        uint2 pa = make_uint2(__float_as_uint(sacc[nf][0] * iA),
                              __float_as_uint(sacc[nf][1] * iA));
        uint2 pb = make_uint2(__float_as_uint(sacc[nf][2] * iB),
                              __float_as_uint(sacc[nf][3] * iB));
        *(uint2*)&smP[rA * 68 + col] = pa;
        *(uint2*)&smP[rB * 68 + col] = pb;
    }
    __syncthreads();

    float oacc[4][4];
#pragma unroll
    for (int nf = 0; nf < 4; nf++)
#pragma unroll
        for (int c = 0; c < 4; c++) oacc[nf][c] = 0.f;

#pragma unroll
    for (int kc = 0; kc < 8; kc++) {
        uint4 afr;
        afr.x = smP[rA * 68 + kc * 8 + tig];
        afr.y = smP[rB * 68 + kc * 8 + tig];
        afr.z = smP[rA * 68 + kc * 8 + tig + 4];
        afr.w = smP[rB * 68 + kc * 8 + tig + 4];
#pragma unroll
        for (int nf = 0; nf < 4; nf++) {
            unsigned bb0 = vs[(kc * 8 + tig) * 40 + nf * 8 + gid];
            unsigned bb1 = vs[(kc * 8 + tig + 4) * 40 + nf * 8 + gid];
            mma_tf32(oacc[nf], afr, bb0, bb1);
        }
    }

    const float third = 1.0f / 3.0f;
    const int tokA = base + off + r * rA;
    const int tokB = base + off + r * rB;
#pragma unroll
    for (int nf = 0; nf < 4; nf++) {
        int col = h * HDIM + nf * 8 + 2 * tig;
        float* pA = &acc[(size_t)tokA * DIM + col];
        float* pB = &acc[(size_t)tokB * DIM + col];
        atomicAdd(pA,     oacc[nf][0] * third);
        atomicAdd(pA + 1, oacc[nf][1] * third);
        atomicAdd(pB,     oacc[nf][2] * third);
        atomicAdd(pB + 1, oacc[nf][3] * third);
    }
}

// ---------------------------------------------------------------------------
// Layer-2 fused tail (per batch). Compact inputs (128 rows/batch).
// ---------------------------------------------------------------------------
__global__ __launch_bounds__(256)
void tail_kernel(const float* __restrict__ x,  const float* __restrict__ hh,
                 const float* __restrict__ k,  const float* __restrict__ v,
                 const float* __restrict__ Wq, const float* __restrict__ Wo,
                 const float* __restrict__ W1, const float* __restrict__ W2,
                 const float* __restrict__ b1v, const float* __restrict__ b2v,
                 const float* __restrict__ ln2s, const float* __restrict__ ln2b,
                 const float* __restrict__ lnfs, const float* __restrict__ lnfb,
                 float* __restrict__ out)
{
    __shared__ float xs[256], hq[256], qsh[256], att[256], x1[256], h2[256];
    __shared__ float f[1024];
    __shared__ float red[4 * 256];
    __shared__ float psh[8][64];
    __shared__ float rsum[8];

    const int b    = blockIdx.x;
    const int t    = threadIdx.x;
    const int lane = t & 31;
    const int wrp  = t >> 5;
    const size_t row0 = (size_t)b * 128 * DIM;

    xs[t] = x[row0 + t];
    hq[t] = hh[row0 + t];
    __syncthreads();

    {
        const int c4 = (t & 63) * 4;
        const int ks = t >> 6;
        float4 a = make_float4(0.f, 0.f, 0.f, 0.f);
        for (int kk = 0; kk < 64; kk++) {
            int ki = ks * 64 + kk;
            float s = hq[ki];
            float4 w = *(const float4*)&Wq[(size_t)ki * 256 + c4];
            a.x += s * w.x; a.y += s * w.y; a.z += s * w.z; a.w += s * w.w;
        }
        *(float4*)&red[ks * 256 + c4] = a;
        __syncthreads();
        qsh[t] = red[t] + red[256 + t] + red[512 + t] + red[768 + t];
        __syncthreads();
    }

    {
        const int h = wrp;
        float o = 0.f;
        const float4* qv = (const float4*)&qsh[h * 32];
#pragma unroll
        for (int c = 0; c < 3; c++) {
            const int r = 1 << c;
            if (h % r == 0) {
                int c0 = cinv(r * lane);
                int c1 = cinv(r * (lane + 32));
                const float4* k0p = (const float4*)(k + ((size_t)(b * 128 + c0) * DIM) + h * 32);
                const float4* k1p = (const float4*)(k + ((size_t)(b * 128 + c1) * DIM) + h * 32);
                float s0 = 0.f, s1 = 0.f;
#pragma unroll
                for (int u = 0; u < 8; u++) {
                    float4 qd = qv[u];
                    float4 ka = k0p[u];
                    float4 kb = k1p[u];
                    s0 += qd.x * ka.x + qd.y * ka.y + qd.z * ka.z + qd.w * ka.w;
                    s1 += qd.x * kb.x + qd.y * kb.y + qd.z * kb.z + qd.w * kb.w;
                }
                s0 *= 0.17677669529663687f;
                s1 *= 0.17677669529663687f;
                float mx = fmaxf(s0, s1);
#pragma unroll
                for (int ofs = 16; ofs > 0; ofs >>= 1)
                    mx = fmaxf(mx, __shfl_xor_sync(0xffffffffu, mx, ofs));
                float e0 = __expf(s0 - mx), e1 = __expf(s1 - mx);
                float sm = wred_sum(e0 + e1);
                float inv = 1.0f / sm;
                psh[h][lane]      = e0 * inv;
                psh[h][lane + 32] = e1 * inv;
                __syncwarp();
                float oc = 0.f;
#pragma unroll 8
                for (int j = 0; j < 64; j++) {
                    int cj = cinv(r * j);
                    oc += psh[h][j] * v[((size_t)(b * 128 + cj) * DIM) + h * 32 + lane];
                }
                o += oc;
                __syncwarp();
            }
        }
        att[h * 32 + lane] = o * (1.0f / 3.0f);
    }
    __syncthreads();

    {
        const int c4 = (t & 63) * 4;
        const int ks = t >> 6;
        float4 a = make_float4(0.f, 0.f, 0.f, 0.f);
        for (int kk = 0; kk < 64; kk++) {
            int ki = ks * 64 + kk;
            float s = att[ki];
            float4 w = *(const float4*)&Wo[(size_t)ki * 256 + c4];
            a.x += s * w.x; a.y += s * w.y; a.z += s * w.z; a.w += s * w.w;
        }
        __syncthreads();
        *(float4*)&red[ks * 256 + c4] = a;
        __syncthreads();
        x1[t] = red[t] + red[256 + t] + red[512 + t] + red[768 + t] + xs[t];
        __syncthreads();
    }

    {
        float val = x1[t];
        float s = wred_sum(val);
        if (lane == 0) rsum[wrp] = s;
        __syncthreads();
        float tot = 0.f;
#pragma unroll
        for (int i = 0; i < 8; i++) tot += rsum[i];
        float mu = tot * (1.0f / 256.0f);
        __syncthreads();
        float dv = val - mu;
        float s2 = wred_sum(dv * dv);
        if (lane == 0) rsum[wrp] = s2;
        __syncthreads();
        float tv = 0.f;
#pragma unroll
        for (int i = 0; i < 8; i++) tv += rsum[i];
        float inv = rsqrtf(tv * (1.0f / 256.0f) + 1e-5f);
        h2[t] = dv * inv * ln2s[t] + ln2b[t];
        __syncthreads();
    }

    {
        const int c4 = t * 4;
        float4 a = make_float4(0.f, 0.f, 0.f, 0.f);
        for (int ki = 0; ki < 256; ki++) {
            float s = h2[ki];
            float4 w = *(const float4*)&W1[(size_t)ki * 1024 + c4];
            a.x += s * w.x; a.y += s * w.y; a.z += s * w.z; a.w += s * w.w;
        }
        float4 bb = *(const float4*)&b1v[c4];
        f[c4 + 0] = gelu_tanh(a.x + bb.x);
        f[c4 + 1] = gelu_tanh(a.y + bb.y);
        f[c4 + 2] = gelu_tanh(a.z + bb.z);
        f[c4 + 3] = gelu_tanh(a.w + bb.w);
        __syncthreads();
    }

    {
        const int c4 = (t & 63) * 4;
        const int ks = t >> 6;
        float4 a = make_float4(0.f, 0.f, 0.f, 0.f);
        for (int kk = 0; kk < 256; kk++) {
            int ki = ks * 256 + kk;
            float s = f[ki];
            float4 w = *(const float4*)&W2[(size_t)ki * 256 + c4];
            a.x += s * w.x; a.y += s * w.y; a.z += s * w.z; a.w += s * w.w;
        }
        *(float4*)&red[ks * 256 + c4] = a;
        __syncthreads();
        float y = red[t] + red[256 + t] + red[512 + t] + red[768 + t] + b2v[t] + x1[t];

        float s = wred_sum(y);
        if (lane == 0) rsum[wrp] = s;
        __syncthreads();
        float tot = 0.f;
#pragma unroll
        for (int i = 0; i < 8; i++) tot += rsum[i];
        float mu = tot * (1.0f / 256.0f);
        __syncthreads();
        float dv = y - mu;
        float s2 = wred_sum(dv * dv);
        if (lane == 0) rsum[wrp] = s2;
        __syncthreads();
        float tv = 0.f;
#pragma unroll
        for (int i = 0; i < 8; i++) tv += rsum[i];
        float inv = rsqrtf(tv * (1.0f / 256.0f) + 1e-5f);
        out[(size_t)b * 256 + t] = dv * inv * lnfs[t] + lnfb[t];
    }
}

// ---------------------------------------------------------------------------
// Orchestration: 9 launches (memset + 8 kernels).
// ---------------------------------------------------------------------------
extern "C" void kernel_launch(void* const* d_in, const int* in_sizes, int n_in,
                              void* d_out, int out_size)
{
    const float* target_feat   = (const float*)d_in[0];
    const float* context_feats = (const float*)d_in[1];
    const float* target_pos    = (const float*)d_in[2];
    const float* context_pos   = (const float*)d_in[3];
    const float* W_proj        = (const float*)d_in[4];
    const float* b_proj        = (const float*)d_in[5];
    const float* Wq            = (const float*)d_in[6];
    const float* Wk            = (const float*)d_in[7];
    const float* Wv            = (const float*)d_in[8];
    const float* Wo            = (const float*)d_in[9];
    const float* ln1_s         = (const float*)d_in[10];
    const float* ln1_b         = (const float*)d_in[11];
    const float* ln2_s         = (const float*)d_in[12];
    const float* ln2_b         = (const float*)d_in[13];
    const float* W1            = (const float*)d_in[14];
    const float* b1            = (const float*)d_in[15];
    const float* W2            = (const float*)d_in[16];
    const float* b2            = (const float*)d_in[17];
    const float* lnf_s         = (const float*)d_in[18];
    const float* lnf_b         = (const float*)d_in[19];
    float* out = (float*)d_out;

    float *x, *h, *q, *k, *v, *accb, *ffn;
    cudaGetSymbolAddress((void**)&x,    g_x);
    cudaGetSymbolAddress((void**)&h,    g_h);
    cudaGetSymbolAddress((void**)&q,    g_q);
    cudaGetSymbolAddress((void**)&k,    g_k);
    cudaGetSymbolAddress((void**)&v,    g_v);
    cudaGetSymbolAddress((void**)&accb, g_acc);
    cudaGetSymbolAddress((void**)&ffn,  g_ffn);

    constexpr int LN32_SMEM = 3 * (32 * 20 + PBSL) * 4;   // 58368
    constexpr int LN16_SMEM = 3 * (16 * 20 + PBSL) * 4;   // 54528

    static bool attr_done = false;
    if (!attr_done) {
        cudaFuncSetAttribute(gemm_pipe_ln<5, 32, 1>,
                             cudaFuncAttributeMaxDynamicSharedMemorySize, LN32_SMEM);
        cudaFuncSetAttribute(gemm_pipe_ln<6, 16, 2>,
                             cudaFuncAttributeMaxDynamicSharedMemorySize, LN16_SMEM);
        cudaFuncSetAttribute(gemm_pipe_ln<3, 16, 0>,
                             cudaFuncAttributeMaxDynamicSharedMemorySize, LN16_SMEM);
        cudaFuncSetAttribute(gemm_pipe<0>,
                             cudaFuncAttributeMaxDynamicSharedMemorySize, GP_SMEM);
        cudaFuncSetAttribute(gemm_pipe<2>,
                             cudaFuncAttributeMaxDynamicSharedMemorySize, GP_SMEM);
        cudaFuncSetAttribute(gemm_pipe32,
                             cudaFuncAttributeMaxDynamicSharedMemorySize, GP32_SMEM);
        attr_done = true;
    }

    const dim3 gProj (1, TOK / 32, 1);                // (1, 128)
    const dim3 gQKV  (DIM / 128, TOK / 64, 3);        // (2, 64, 3)
    const dim3 gWo   (1, CTOK / 16, 1);               // (1, 128)
    const dim3 gFFN1 (FFN_DIM / 128, CTOK / 64, 1);   // (8, 32)
    const dim3 gFFN2 (1, CTOK / 16, 1);               // (1, 128)
    const dim3 gKV   (DIM / 128, CTOK / 32, 2);       // (2, 64, 2)

    // 0. Zero attention accumulator
    cudaMemsetAsync(accb, 0, (size_t)TOK * DIM * sizeof(float));

    // 1. proj (+bias+posenc) + LN1 fused epilogue -> x (raw), h (normalized)
    gemm_pipe_ln<5, 32, 1><<<gProj, 256, LN32_SMEM>>>(
        nullptr, W_proj, b_proj, nullptr, ln1_s, ln1_b,
        x, h, INDIM,
        target_feat, context_feats, target_pos, context_pos);

    // 2. QKV fused (full)
    gemm_pipe<0><<<gQKV, 256, GP_SMEM>>>(
        h, Wq, Wk, Wv, nullptr, q, k, v, DIM, DIM);

    // 3. Attention (atomic-add into accb)
    attn_all_kernel<<<896, 128>>>(q, k, v, accb);

    // 4. Wo + residual(cmap) + LN2 fused -> x1c (g_q raw), h (normalized, compact)
    gemm_pipe_ln<6, 16, 2><<<gWo, 256, LN16_SMEM>>>(
        accb, Wo, nullptr, x, ln2_s, ln2_b,
        q, h, DIM,
        nullptr, nullptr, nullptr, nullptr);

    // 5. FFN1 compact: ffn = gelu(h @ W1 + b1)
    gemm_pipe<2><<<gFFN1, 256, GP_SMEM>>>(
        h, W1, nullptr, nullptr, b1, ffn, nullptr, nullptr, FFN_DIM, DIM);

    // 6. FFN2 + b2 + residual(x1c) + LN1(l2) fused -> x2c (g_x raw), h (norm)
    gemm_pipe_ln<3, 16, 0><<<gFFN2, 256, LN16_SMEM>>>(
        ffn, W2, b2, q, ln1_s + DIM, ln1_b + DIM,
        x, h, FFN_DIM,
        nullptr, nullptr, nullptr, nullptr);

    // 7. K,V compact (z=2)
    gemm_pipe32<<<gKV, 128, GP32_SMEM>>>(
        h, Wk + DIM * DIM, Wv + DIM * DIM, k, v, DIM, DIM);

    // 8. Fused tail (compact inputs)
    tail_kernel<<<BATCH, 256>>>(
        x, h, k, v,
        Wq + DIM * DIM, Wo + DIM * DIM,
        W1 + DIM * FFN_DIM, W2 + FFN_DIM * DIM,
        b1 + FFN_DIM, b2 + DIM,
        ln2_s + DIM, ln2_b + DIM, lnf_s, lnf_b, out);
}

// round 17
// speedup vs baseline: 1.0454x; 1.0454x over previous
#include <cuda_runtime.h>
#include <math.h>

// ---------------------------------------------------------------------------
// GlobalLocalAwareEncoder — truncated-dependency implementation (R14 base).
// T1: dilated segments never cross 256-token boundaries.
// T2: only token 0 per batch feeds the output (fused tail).
// T3: layer-2 needs only a 128-token compact set per batch (2048 rows).
// GEMMs: cp.async 3-stage pipelined tf32 MMA, BK=32, raw fp32 (implicit RZ).
// R17: proj moved to the BM=32/128-thread pipe (grid 256 CTAs, 2-3 CTAs/SM)
// with feats-gather + posenc epilogue.
// ---------------------------------------------------------------------------

#define BATCH   16
#define SEQ     256
#define TOK     (BATCH * SEQ)   // 4096
#define CTOK    (BATCH * 128)   // 2048 compact rows
#define DIM     256
#define HEADS   8
#define HDIM    32
#define FFN_DIM 1024
#define INDIM   512
#define NCTX    4095

__device__ float g_x  [TOK * DIM];
__device__ float g_h  [TOK * DIM];
__device__ float g_q  [TOK * DIM];
__device__ float g_k  [TOK * DIM];
__device__ float g_v  [TOK * DIM];
__device__ float g_acc[TOK * DIM];
__device__ float g_ffn[TOK * FFN_DIM];

// compact index <-> token maps (per batch)
__device__ __forceinline__ int cmap(int c) {
    return c < 64 ? c : (c < 96 ? 64 + 2 * (c - 64) : 128 + 4 * (c - 96));
}
__device__ __forceinline__ int cinv(int tok) {
    return tok < 64 ? tok : (tok < 128 ? 64 + ((tok - 64) >> 1)
                                       : 96 + ((tok - 128) >> 2));
}

__device__ __forceinline__ float gelu_tanh(float x) {
    float x3 = x * x * x;
    return 0.5f * x * (1.0f + tanhf(0.7978845608028654f * (x + 0.044715f * x3)));
}

__device__ __forceinline__ void mma_tf32(float* d, uint4 a, unsigned b0, unsigned b1) {
    asm volatile(
        "mma.sync.aligned.m16n8k8.row.col.f32.tf32.tf32.f32 "
        "{%0,%1,%2,%3}, {%4,%5,%6,%7}, {%8,%9}, {%0,%1,%2,%3};"
        : "+f"(d[0]), "+f"(d[1]), "+f"(d[2]), "+f"(d[3])
        : "r"(a.x), "r"(a.y), "r"(a.z), "r"(a.w), "r"(b0), "r"(b1));
}

__device__ __forceinline__ void cpa16(unsigned dst, const float* src) {
    asm volatile("cp.async.cg.shared.global [%0], [%1], 16;" :: "r"(dst), "l"(src));
}

__device__ __forceinline__ float wred_sum(float v) {
#pragma unroll
    for (int o = 16; o > 0; o >>= 1) v += __shfl_xor_sync(0xffffffffu, v, o);
    return v;
}

__device__ __forceinline__ float pe_val(int row, int col,
                                        const float* __restrict__ tpos,
                                        const float* __restrict__ cpos) {
    int b = row >> 8, s = row & 255;
    const float* pp = (s == 0) ? (tpos + (size_t)b * 2)
                               : (cpos + ((size_t)b * NCTX + (s - 1)) * 2);
    float pos = (col < 128) ? pp[0] : pp[1];
    int dd = col & 127;
    int i  = dd & 63;
    float omega = expf(-(float)i * (9.210340371976184f / 64.0f));
    float ang = pos * omega;
    return (dd < 64) ? sinf(ang) : cosf(ang);
}

// ---------------------------------------------------------------------------
// Pipelined tf32 GEMM, BM=64, BN=128, BK=32, 3-stage, 256 threads.
// EPI: 0 store / 2 gelu(v+bias). blockIdx.z selects B/C.
// ---------------------------------------------------------------------------
#define PAS  2304   // 64*36
#define PBS  4352   // 32*136
#define GP_SMEM (3 * (PAS + PBS) * 4)

template<int EPI>
__global__ __launch_bounds__(256)
void gemm_pipe(const float* __restrict__ A,
               const float* __restrict__ B0, const float* __restrict__ B1,
               const float* __restrict__ B2,
               const float* __restrict__ bias,
               float* __restrict__ C0, float* __restrict__ C1, float* __restrict__ C2,
               int N, int K)
{
    extern __shared__ float sm[];
    float* AsB = sm;
    float* BsB = sm + 3 * PAS;

    const int z = blockIdx.z;
    const float* B = (z == 0) ? B0 : (z == 1) ? B1 : B2;
    float*       C = (z == 0) ? C0 : (z == 1) ? C1 : C2;

    const int t    = threadIdx.x;
    const int lane = t & 31;
    const int warp = t >> 5;
    const int wm   = warp >> 2;
    const int wn   = warp & 3;
    const int gid  = lane >> 2;
    const int tig  = lane & 3;

    const int bm = blockIdx.y * 64;
    const int bn = blockIdx.x * 128;

    const float* aptr[2];
    unsigned a_dst[2];
#pragma unroll
    for (int i = 0; i < 2; i++) {
        int idx  = t + 256 * i;
        int arow = idx >> 3;
        int acq  = (idx & 7) * 4;
        aptr[i] = A + (size_t)(bm + arow) * K + acq;
        a_dst[i] = (unsigned)__cvta_generic_to_shared(AsB + arow * 36 + acq);
    }

    int b_kr[4], b_nq[4];
    unsigned b_dst[4];
#pragma unroll
    for (int i = 0; i < 4; i++) {
        int idx = t + 256 * i;
        b_kr[i] = idx >> 5;
        b_nq[i] = (idx & 31) * 4;
        b_dst[i] = (unsigned)__cvta_generic_to_shared(BsB + b_kr[i] * 136 + b_nq[i]);
    }

    const int nchunks = K >> 5;

    auto issue = [&](int c) {
        if (c < nchunks) {
            int st = c % 3;
            cpa16(a_dst[0] + st * PAS * 4, aptr[0] + c * 32);
            cpa16(a_dst[1] + st * PAS * 4, aptr[1] + c * 32);
#pragma unroll
            for (int i = 0; i < 4; i++) {
                const float* src = B + (size_t)(c * 32 + b_kr[i]) * N + bn + b_nq[i];
                cpa16(b_dst[i] + st * PBS * 4, src);
            }
        }
        asm volatile("cp.async.commit_group;");
    };

    float accd[2][4][4];
#pragma unroll
    for (int mf = 0; mf < 2; mf++)
#pragma unroll
        for (int nf = 0; nf < 4; nf++)
#pragma unroll
            for (int r = 0; r < 4; r++) accd[mf][nf][r] = 0.f;

    issue(0);
    issue(1);

    for (int c = 0; c < nchunks; c++) {
        asm volatile("cp.async.wait_group 1;");
        __syncthreads();
        issue(c + 2);

        const int st = c % 3;
        const float* Asp = AsB + st * PAS;
        const float* Bsp = BsB + st * PBS;
#pragma unroll
        for (int kf = 0; kf < 4; kf++) {
            uint4 afr[2];
#pragma unroll
            for (int mf = 0; mf < 2; mf++) {
                int rb = wm * 32 + mf * 16;
                afr[mf].x = __float_as_uint(Asp[(rb + gid)     * 36 + kf * 8 + tig]);
                afr[mf].y = __float_as_uint(Asp[(rb + 8 + gid) * 36 + kf * 8 + tig]);
                afr[mf].z = __float_as_uint(Asp[(rb + gid)     * 36 + kf * 8 + tig + 4]);
                afr[mf].w = __float_as_uint(Asp[(rb + 8 + gid) * 36 + kf * 8 + tig + 4]);
            }
#pragma unroll
            for (int nf = 0; nf < 4; nf++) {
                int cb = wn * 32 + nf * 8 + gid;
                unsigned bb0 = __float_as_uint(Bsp[(kf * 8 + tig)     * 136 + cb]);
                unsigned bb1 = __float_as_uint(Bsp[(kf * 8 + tig + 4) * 136 + cb]);
                mma_tf32(accd[0][nf], afr[0], bb0, bb1);
                mma_tf32(accd[1][nf], afr[1], bb0, bb1);
            }
        }
    }

#pragma unroll
    for (int mf = 0; mf < 2; mf++) {
#pragma unroll
        for (int nf = 0; nf < 4; nf++) {
            int row = bm + wm * 32 + mf * 16 + gid;
            int col = bn + wn * 32 + nf * 8 + 2 * tig;
#pragma unroll
            for (int half = 0; half < 2; half++) {
                int r = row + half * 8;
                float v0 = accd[mf][nf][half * 2 + 0];
                float v1 = accd[mf][nf][half * 2 + 1];
                size_t idx = (size_t)r * N + col;
                if (EPI == 2) {
                    v0 = gelu_tanh(v0 + bias[col]);
                    v1 = gelu_tanh(v1 + bias[col + 1]);
                }
                *(float2*)&C[idx] = make_float2(v0, v1);
            }
        }
    }
}

// ---------------------------------------------------------------------------
// Pipelined tf32 GEMM, BM=32, BN=128, BK=32, 3-stage, 128 threads (4 warps,
// warp tile 32x32). Dynamic smem: 66048 B -> up to 3 CTAs/SM.
// GMODE: 0 plain A / 1 gather target/context feats (full rows, K=INDIM) /
//        2 gather compact rows via cmap from full-token buffer.
// EPI: 0 store / 3 v+res(+bias), compact res / 5 v+bias+0.3*posenc /
//      6 v+res, res full-token (row cmap'd).
// blockIdx.z selects B/C.
// ---------------------------------------------------------------------------
#define PAS32 1152   // 32*36
#define PBS32 4352   // 32*136
#define GP32_SMEM (3 * (PAS32 + PBS32) * 4)

template<int EPI, int GMODE>
__global__ __launch_bounds__(128)
void gemm_pipe32(const float* __restrict__ A,
                 const float* __restrict__ B0, const float* __restrict__ B1,
                 const float* __restrict__ bias, const float* __restrict__ res,
                 float* __restrict__ C0, float* __restrict__ C1,
                 int N, int K,
                 const float* __restrict__ tfeat, const float* __restrict__ cfeat,
                 const float* __restrict__ tpos,  const float* __restrict__ cpos)
{
    extern __shared__ float sm[];
    float* AsB = sm;
    float* BsB = sm + 3 * PAS32;

    const int z = blockIdx.z;
    const float* B = (z == 0) ? B0 : B1;
    float*       C = (z == 0) ? C0 : C1;

    const int t    = threadIdx.x;
    const int lane = t & 31;
    const int wn   = t >> 5;            // 0..3 (warp = n-tile)
    const int gid  = lane >> 2;
    const int tig  = lane & 3;

    const int bm = blockIdx.y * 32;
    const int bn = blockIdx.x * 128;

    // A fill: 256 cpa16/chunk, 2/thread
    const float* aptr[2];
    unsigned a_dst[2];
#pragma unroll
    for (int i = 0; i < 2; i++) {
        int idx  = t + 128 * i;
        int arow = idx >> 3;            // 0..31
        int acq  = (idx & 7) * 4;
        if (GMODE == 1) {
            int row = bm + arow;
            int bi = row >> 8, s = row & 255;
            const float* rp = (s == 0) ? (tfeat + (size_t)bi * INDIM)
                                       : (cfeat + ((size_t)bi * NCTX + (s - 1)) * INDIM);
            aptr[i] = rp + acq;
        } else if (GMODE == 2) {
            int row = bm + arow;
            int bi = row >> 7;
            int tok = cmap(row & 127);
            aptr[i] = A + (size_t)(bi * 256 + tok) * K + acq;
        } else {
            aptr[i] = A + (size_t)(bm + arow) * K + acq;
        }
        a_dst[i] = (unsigned)__cvta_generic_to_shared(AsB + arow * 36 + acq);
    }

    // B fill: 1024 cpa16/chunk, 8/thread
    int b_kr[8], b_nq[8];
    unsigned b_dst[8];
#pragma unroll
    for (int i = 0; i < 8; i++) {
        int idx = t + 128 * i;
        b_kr[i] = idx >> 5;             // 0..31
        b_nq[i] = (idx & 31) * 4;
        b_dst[i] = (unsigned)__cvta_generic_to_shared(BsB + b_kr[i] * 136 + b_nq[i]);
    }

    const int nchunks = K >> 5;

    auto issue = [&](int c) {
        if (c < nchunks) {
            int st = c % 3;
            cpa16(a_dst[0] + st * PAS32 * 4, aptr[0] + c * 32);
            cpa16(a_dst[1] + st * PAS32 * 4, aptr[1] + c * 32);
#pragma unroll
            for (int i = 0; i < 8; i++) {
                const float* src = B + (size_t)(c * 32 + b_kr[i]) * N + bn + b_nq[i];
                cpa16(b_dst[i] + st * PBS32 * 4, src);
            }
        }
        asm volatile("cp.async.commit_group;");
    };

    float accd[2][4][4];
#pragma unroll
    for (int mf = 0; mf < 2; mf++)
#pragma unroll
        for (int nf = 0; nf < 4; nf++)
#pragma unroll
            for (int r = 0; r < 4; r++) accd[mf][nf][r] = 0.f;

    issue(0);
    issue(1);

    for (int c = 0; c < nchunks; c++) {
        asm volatile("cp.async.wait_group 1;");
        __syncthreads();
        issue(c + 2);

        const int st = c % 3;
        const float* Asp = AsB + st * PAS32;
        const float* Bsp = BsB + st * PBS32;
#pragma unroll
        for (int kf = 0; kf < 4; kf++) {
            uint4 afr[2];
#pragma unroll
            for (int mf = 0; mf < 2; mf++) {
                int rb = mf * 16;
                afr[mf].x = __float_as_uint(Asp[(rb + gid)     * 36 + kf * 8 + tig]);
                afr[mf].y = __float_as_uint(Asp[(rb + 8 + gid) * 36 + kf * 8 + tig]);
                afr[mf].z = __float_as_uint(Asp[(rb + gid)     * 36 + kf * 8 + tig + 4]);
                afr[mf].w = __float_as_uint(Asp[(rb + 8 + gid) * 36 + kf * 8 + tig + 4]);
            }
#pragma unroll
            for (int nf = 0; nf < 4; nf++) {
                int cb = wn * 32 + nf * 8 + gid;
                unsigned bb0 = __float_as_uint(Bsp[(kf * 8 + tig)     * 136 + cb]);
                unsigned bb1 = __float_as_uint(Bsp[(kf * 8 + tig + 4) * 136 + cb]);
                mma_tf32(accd[0][nf], afr[0], bb0, bb1);
                mma_tf32(accd[1][nf], afr[1], bb0, bb1);
            }
        }
    }

#pragma unroll
    for (int mf = 0; mf < 2; mf++) {
#pragma unroll
        for (int nf = 0; nf < 4; nf++) {
            int row = bm + mf * 16 + gid;
            int col = bn + wn * 32 + nf * 8 + 2 * tig;
#pragma unroll
            for (int half = 0; half < 2; half++) {
                int r = row + half * 8;
                float v0 = accd[mf][nf][half * 2 + 0];
                float v1 = accd[mf][nf][half * 2 + 1];
                size_t idx = (size_t)r * N + col;
                if (EPI == 3) {
                    if (bias) { v0 += bias[col]; v1 += bias[col + 1]; }
                    v0 += res[idx]; v1 += res[idx + 1];
                } else if (EPI == 5) {
                    v0 += bias[col]     + 0.3f * pe_val(r, col,     tpos, cpos);
                    v1 += bias[col + 1] + 0.3f * pe_val(r, col + 1, tpos, cpos);
                } else if (EPI == 6) {
                    int bi = r >> 7;
                    int tok = cmap(r & 127);
                    size_t ridx = (size_t)(bi * 256 + tok) * N + col;
                    v0 += res[ridx]; v1 += res[ridx + 1];
                }
                *(float2*)&C[idx] = make_float2(v0, v1);
            }
        }
    }
}

// ---------------------------------------------------------------------------
// LayerNorm: one warp per token, D=256.
// ---------------------------------------------------------------------------
__global__ void ln_kernel(const float* __restrict__ x, const float* __restrict__ sc,
                          const float* __restrict__ bi, float* __restrict__ out,
                          int ntok, int in_stride)
{
    int gw   = (blockIdx.x * blockDim.x + threadIdx.x) >> 5;
    int lane = threadIdx.x & 31;
    if (gw >= ntok) return;
    const float* xp = x + (size_t)gw * in_stride;
    float4 v0 = *(const float4*)&xp[lane * 4];
    float4 v1 = *(const float4*)&xp[128 + lane * 4];
    float va[8] = {v0.x, v0.y, v0.z, v0.w, v1.x, v1.y, v1.z, v1.w};

    float s = 0.f;
#pragma unroll
    for (int c = 0; c < 8; c++) s += va[c];
    s = wred_sum(s);
    float mu = s * (1.0f / 256.0f);

    float ss = 0.f;
#pragma unroll
    for (int c = 0; c < 8; c++) { float d = va[c] - mu; ss += d * d; }
    ss = wred_sum(ss);
    float inv = rsqrtf(ss * (1.0f / 256.0f) + 1e-5f);

    float ovals[8];
#pragma unroll
    for (int c = 0; c < 8; c++) {
        int d = (c < 4) ? (lane * 4 + c) : (128 + lane * 4 + (c - 4));
        ovals[c] = (va[c] - mu) * inv * sc[d] + bi[d];
    }
    float* op = out + (size_t)gw * 256;
    *(float4*)&op[lane * 4]       = make_float4(ovals[0], ovals[1], ovals[2], ovals[3]);
    *(float4*)&op[128 + lane * 4] = make_float4(ovals[4], ovals[5], ovals[6], ovals[7]);
}

// ---------------------------------------------------------------------------
// Layer-1 dilated attention on tf32 tensor cores (grid 896, 128 threads).
// Raw-fp32 smem; all configs atomicAdd o/3 into acc (zeroed).
// ---------------------------------------------------------------------------
__global__ __launch_bounds__(128)
void attn_all_kernel(const float* __restrict__ q, const float* __restrict__ k,
                     const float* __restrict__ v, float* __restrict__ acc)
{
    __shared__ unsigned sh[64 * 36 * 2 + 64 * 40];
    unsigned* qs  = sh;
    unsigned* ks  = sh + 64 * 36;
    unsigned* vs  = sh + 64 * 72;
    unsigned* smP = sh;

    int bid = blockIdx.x;
    int r, w;
    if (bid < 512)      { w = 64;  r = 1; }
    else if (bid < 768) { bid -= 512; w = 128; r = 2; }
    else                { bid -= 768; w = 256; r = 4; }

    const int nseg = SEQ / w;
    const int h   = bid & 7;
    const int seg = (bid >> 3) % nseg;
    const int b   = bid / (8 * nseg);
    const int base = b * SEQ + seg * w;
    const int off  = h % r;
    const int t    = threadIdx.x;
    const int lane = t & 31;
    const int wrp  = t >> 5;
    const int gid  = lane >> 2;
    const int tig  = lane & 3;

#pragma unroll
    for (int i = 0; i < 4; i++) {
        int idx = t + 128 * i;
        int j  = idx >> 3;
        int dq = (idx & 7) * 4;
        int tok = base + off + r * j;
        size_t gi = (size_t)tok * DIM + h * HDIM + dq;
        cpa16((unsigned)__cvta_generic_to_shared(&qs[j * 36 + dq]), &q[gi]);
        cpa16((unsigned)__cvta_generic_to_shared(&ks[j * 36 + dq]), &k[gi]);
        cpa16((unsigned)__cvta_generic_to_shared(&vs[j * 40 + dq]), &v[gi]);
    }
    asm volatile("cp.async.commit_group;");
    asm volatile("cp.async.wait_group 0;");
    __syncthreads();

    const int rA = wrp * 16 + gid;
    const int rB = rA + 8;
    float sacc[8][4];
#pragma unroll
    for (int nf = 0; nf < 8; nf++)
#pragma unroll
        for (int c = 0; c < 4; c++) sacc[nf][c] = 0.f;

#pragma unroll
    for (int kc = 0; kc < 4; kc++) {
        uint4 afr;
        afr.x = qs[rA * 36 + kc * 8 + tig];
        afr.y = qs[rB * 36 + kc * 8 + tig];
        afr.z = qs[rA * 36 + kc * 8 + tig + 4];
        afr.w = qs[rB * 36 + kc * 8 + tig + 4];
#pragma unroll
        for (int nf = 0; nf < 8; nf++) {
            unsigned bb0 = ks[(nf * 8 + gid) * 36 + kc * 8 + tig];
            unsigned bb1 = ks[(nf * 8 + gid) * 36 + kc * 8 + tig + 4];
            mma_tf32(sacc[nf], afr, bb0, bb1);
        }
    }

    const float scl = 0.17677669529663687f;
    float mA = -1e30f, mB = -1e30f;
#pragma unroll
    for (int nf = 0; nf < 8; nf++) {
        sacc[nf][0] *= scl; sacc[nf][1] *= scl;
        sacc[nf][2] *= scl; sacc[nf][3] *= scl;
        mA = fmaxf(mA, fmaxf(sacc[nf][0], sacc[nf][1]));
        mB = fmaxf(mB, fmaxf(sacc[nf][2], sacc[nf][3]));
    }
#pragma unroll
    for (int o = 2; o > 0; o >>= 1) {
        mA = fmaxf(mA, __shfl_xor_sync(0xffffffffu, mA, o));
        mB = fmaxf(mB, __shfl_xor_sync(0xffffffffu, mB, o));
    }
    float sA = 0.f, sB = 0.f;
#pragma unroll
    for (int nf = 0; nf < 8; nf++) {
        sacc[nf][0] = __expf(sacc[nf][0] - mA); sA += sacc[nf][0];
        sacc[nf][1] = __expf(sacc[nf][1] - mA); sA += sacc[nf][1];
        sacc[nf][2] = __expf(sacc[nf][2] - mB); sB += sacc[nf][2];
        sacc[nf][3] = __expf(sacc[nf][3] - mB); sB += sacc[nf][3];
    }
#pragma unroll
    for (int o = 2; o > 0; o >>= 1) {
        sA += __shfl_xor_sync(0xffffffffu, sA, o);
        sB += __shfl_xor_sync(0xffffffffu, sB, o);
    }
    const float iA = 1.0f / sA, iB = 1.0f / sB;

    __syncthreads();

#pragma unroll
    for (int nf = 0; nf < 8; nf++) {
        int col = nf * 8 + 2 * tig;
        uint2 pa = make_uint2(__float_as_uint(sacc[nf][0] * iA),
                              __float_as_uint(sacc[nf][1] * iA));
        uint2 pb = make_uint2(__float_as_uint(sacc[nf][2] * iB),
                              __float_as_uint(sacc[nf][3] * iB));
        *(uint2*)&smP[rA * 68 + col] = pa;
        *(uint2*)&smP[rB * 68 + col] = pb;
    }
    __syncthreads();

    float oacc[4][4];
#pragma unroll
    for (int nf = 0; nf < 4; nf++)
#pragma unroll
        for (int c = 0; c < 4; c++) oacc[nf][c] = 0.f;

#pragma unroll
    for (int kc = 0; kc < 8; kc++) {
        uint4 afr;
        afr.x = smP[rA * 68 + kc * 8 + tig];
        afr.y = smP[rB * 68 + kc * 8 + tig];
        afr.z = smP[rA * 68 + kc * 8 + tig + 4];
        afr.w = smP[rB * 68 + kc * 8 + tig + 4];
#pragma unroll
        for (int nf = 0; nf < 4; nf++) {
            unsigned bb0 = vs[(kc * 8 + tig) * 40 + nf * 8 + gid];
            unsigned bb1 = vs[(kc * 8 + tig + 4) * 40 + nf * 8 + gid];
            mma_tf32(oacc[nf], afr, bb0, bb1);
        }
    }

    const float third = 1.0f / 3.0f;
    const int tokA = base + off + r * rA;
    const int tokB = base + off + r * rB;
#pragma unroll
    for (int nf = 0; nf < 4; nf++) {
        int col = h * HDIM + nf * 8 + 2 * tig;
        float* pA = &acc[(size_t)tokA * DIM + col];
        float* pB = &acc[(size_t)tokB * DIM + col];
        atomicAdd(pA,     oacc[nf][0] * third);
        atomicAdd(pA + 1, oacc[nf][1] * third);
        atomicAdd(pB,     oacc[nf][2] * third);
        atomicAdd(pB + 1, oacc[nf][3] * third);
    }
}

// ---------------------------------------------------------------------------
// Layer-2 fused tail (per batch). Compact inputs (128 rows/batch).
// ---------------------------------------------------------------------------
__global__ __launch_bounds__(256)
void tail_kernel(const float* __restrict__ x,  const float* __restrict__ hh,
                 const float* __restrict__ k,  const float* __restrict__ v,
                 const float* __restrict__ Wq, const float* __restrict__ Wo,
                 const float* __restrict__ W1, const float* __restrict__ W2,
                 const float* __restrict__ b1v, const float* __restrict__ b2v,
                 const float* __restrict__ ln2s, const float* __restrict__ ln2b,
                 const float* __restrict__ lnfs, const float* __restrict__ lnfb,
                 float* __restrict__ out)
{
    __shared__ float xs[256], hq[256], qsh[256], att[256], x1[256], h2[256];
    __shared__ float f[1024];
    __shared__ float red[4 * 256];
    __shared__ float psh[8][64];
    __shared__ float rsum[8];

    const int b    = blockIdx.x;
    const int t    = threadIdx.x;
    const int lane = t & 31;
    const int wrp  = t >> 5;
    const size_t row0 = (size_t)b * 128 * DIM;

    xs[t] = x[row0 + t];
    hq[t] = hh[row0 + t];
    __syncthreads();

    {
        const int c4 = (t & 63) * 4;
        const int ks = t >> 6;
        float4 a = make_float4(0.f, 0.f, 0.f, 0.f);
        for (int kk = 0; kk < 64; kk++) {
            int ki = ks * 64 + kk;
            float s = hq[ki];
            float4 w = *(const float4*)&Wq[(size_t)ki * 256 + c4];
            a.x += s * w.x; a.y += s * w.y; a.z += s * w.z; a.w += s * w.w;
        }
        *(float4*)&red[ks * 256 + c4] = a;
        __syncthreads();
        qsh[t] = red[t] + red[256 + t] + red[512 + t] + red[768 + t];
        __syncthreads();
    }

    {
        const int h = wrp;
        float o = 0.f;
        const float4* qv = (const float4*)&qsh[h * 32];
#pragma unroll
        for (int c = 0; c < 3; c++) {
            const int r = 1 << c;
            if (h % r == 0) {
                int c0 = cinv(r * lane);
                int c1 = cinv(r * (lane + 32));
                const float4* k0p = (const float4*)(k + ((size_t)(b * 128 + c0) * DIM) + h * 32);
                const float4* k1p = (const float4*)(k + ((size_t)(b * 128 + c1) * DIM) + h * 32);
                float s0 = 0.f, s1 = 0.f;
#pragma unroll
                for (int u = 0; u < 8; u++) {
                    float4 qd = qv[u];
                    float4 ka = k0p[u];
                    float4 kb = k1p[u];
                    s0 += qd.x * ka.x + qd.y * ka.y + qd.z * ka.z + qd.w * ka.w;
                    s1 += qd.x * kb.x + qd.y * kb.y + qd.z * kb.z + qd.w * kb.w;
                }
                s0 *= 0.17677669529663687f;
                s1 *= 0.17677669529663687f;
                float mx = fmaxf(s0, s1);
#pragma unroll
                for (int ofs = 16; ofs > 0; ofs >>= 1)
                    mx = fmaxf(mx, __shfl_xor_sync(0xffffffffu, mx, ofs));
                float e0 = __expf(s0 - mx), e1 = __expf(s1 - mx);
                float sm = wred_sum(e0 + e1);
                float inv = 1.0f / sm;
                psh[h][lane]      = e0 * inv;
                psh[h][lane + 32] = e1 * inv;
                __syncwarp();
                float oc = 0.f;
#pragma unroll 8
                for (int j = 0; j < 64; j++) {
                    int cj = cinv(r * j);
                    oc += psh[h][j] * v[((size_t)(b * 128 + cj) * DIM) + h * 32 + lane];
                }
                o += oc;
                __syncwarp();
            }
        }
        att[h * 32 + lane] = o * (1.0f / 3.0f);
    }
    __syncthreads();

    {
        const int c4 = (t & 63) * 4;
        const int ks = t >> 6;
        float4 a = make_float4(0.f, 0.f, 0.f, 0.f);
        for (int kk = 0; kk < 64; kk++) {
            int ki = ks * 64 + kk;
            float s = att[ki];
            float4 w = *(const float4*)&Wo[(size_t)ki * 256 + c4];
            a.x += s * w.x; a.y += s * w.y; a.z += s * w.z; a.w += s * w.w;
        }
        __syncthreads();
        *(float4*)&red[ks * 256 + c4] = a;
        __syncthreads();
        x1[t] = red[t] + red[256 + t] + red[512 + t] + red[768 + t] + xs[t];
        __syncthreads();
    }

    {
        float val = x1[t];
        float s = wred_sum(val);
        if (lane == 0) rsum[wrp] = s;
        __syncthreads();
        float tot = 0.f;
#pragma unroll
        for (int i = 0; i < 8; i++) tot += rsum[i];
        float mu = tot * (1.0f / 256.0f);
        __syncthreads();
        float dv = val - mu;
        float s2 = wred_sum(dv * dv);
        if (lane == 0) rsum[wrp] = s2;
        __syncthreads();
        float tv = 0.f;
#pragma unroll
        for (int i = 0; i < 8; i++) tv += rsum[i];
        float inv = rsqrtf(tv * (1.0f / 256.0f) + 1e-5f);
        h2[t] = dv * inv * ln2s[t] + ln2b[t];
        __syncthreads();
    }

    {
        const int c4 = t * 4;
        float4 a = make_float4(0.f, 0.f, 0.f, 0.f);
        for (int ki = 0; ki < 256; ki++) {
            float s = h2[ki];
            float4 w = *(const float4*)&W1[(size_t)ki * 1024 + c4];
            a.x += s * w.x; a.y += s * w.y; a.z += s * w.z; a.w += s * w.w;
        }
        float4 bb = *(const float4*)&b1v[c4];
        f[c4 + 0] = gelu_tanh(a.x + bb.x);
        f[c4 + 1] = gelu_tanh(a.y + bb.y);
        f[c4 + 2] = gelu_tanh(a.z + bb.z);
        f[c4 + 3] = gelu_tanh(a.w + bb.w);
        __syncthreads();
    }

    {
        const int c4 = (t & 63) * 4;
        const int ks = t >> 6;
        float4 a = make_float4(0.f, 0.f, 0.f, 0.f);
        for (int kk = 0; kk < 256; kk++) {
            int ki = ks * 256 + kk;
            float s = f[ki];
            float4 w = *(const float4*)&W2[(size_t)ki * 256 + c4];
            a.x += s * w.x; a.y += s * w.y; a.z += s * w.z; a.w += s * w.w;
        }
        *(float4*)&red[ks * 256 + c4] = a;
        __syncthreads();
        float y = red[t] + red[256 + t] + red[512 + t] + red[768 + t] + b2v[t] + x1[t];

        float s = wred_sum(y);
        if (lane == 0) rsum[wrp] = s;
        __syncthreads();
        float tot = 0.f;
#pragma unroll
        for (int i = 0; i < 8; i++) tot += rsum[i];
        float mu = tot * (1.0f / 256.0f);
        __syncthreads();
        float dv = y - mu;
        float s2 = wred_sum(dv * dv);
        if (lane == 0) rsum[wrp] = s2;
        __syncthreads();
        float tv = 0.f;
#pragma unroll
        for (int i = 0; i < 8; i++) tv += rsum[i];
        float inv = rsqrtf(tv * (1.0f / 256.0f) + 1e-5f);
        out[(size_t)b * 256 + t] = dv * inv * lnfs[t] + lnfb[t];
    }
}

// ---------------------------------------------------------------------------
// Orchestration (R14 schedule; proj on the BM=32 pipe, grid 256 CTAs)
// ---------------------------------------------------------------------------
extern "C" void kernel_launch(void* const* d_in, const int* in_sizes, int n_in,
                              void* d_out, int out_size)
{
    const float* target_feat   = (const float*)d_in[0];
    const float* context_feats = (const float*)d_in[1];
    const float* target_pos    = (const float*)d_in[2];
    const float* context_pos   = (const float*)d_in[3];
    const float* W_proj        = (const float*)d_in[4];
    const float* b_proj        = (const float*)d_in[5];
    const float* Wq            = (const float*)d_in[6];
    const float* Wk            = (const float*)d_in[7];
    const float* Wv            = (const float*)d_in[8];
    const float* Wo            = (const float*)d_in[9];
    const float* ln1_s         = (const float*)d_in[10];
    const float* ln1_b         = (const float*)d_in[11];
    const float* ln2_s         = (const float*)d_in[12];
    const float* ln2_b         = (const float*)d_in[13];
    const float* W1            = (const float*)d_in[14];
    const float* b1            = (const float*)d_in[15];
    const float* W2            = (const float*)d_in[16];
    const float* b2            = (const float*)d_in[17];
    const float* lnf_s         = (const float*)d_in[18];
    const float* lnf_b         = (const float*)d_in[19];
    float* out = (float*)d_out;

    float *x, *h, *q, *k, *v, *accb, *ffn;
    cudaGetSymbolAddress((void**)&x,    g_x);
    cudaGetSymbolAddress((void**)&h,    g_h);
    cudaGetSymbolAddress((void**)&q,    g_q);
    cudaGetSymbolAddress((void**)&k,    g_k);
    cudaGetSymbolAddress((void**)&v,    g_v);
    cudaGetSymbolAddress((void**)&accb, g_acc);
    cudaGetSymbolAddress((void**)&ffn,  g_ffn);

    static bool attr_done = false;
    if (!attr_done) {
        cudaFuncSetAttribute(gemm_pipe<0>,
                             cudaFuncAttributeMaxDynamicSharedMemorySize, GP_SMEM);
        cudaFuncSetAttribute(gemm_pipe<2>,
                             cudaFuncAttributeMaxDynamicSharedMemorySize, GP_SMEM);
        cudaFuncSetAttribute(gemm_pipe32<5, 1>,
                             cudaFuncAttributeMaxDynamicSharedMemorySize, GP32_SMEM);
        cudaFuncSetAttribute(gemm_pipe32<6, 2>,
                             cudaFuncAttributeMaxDynamicSharedMemorySize, GP32_SMEM);
        cudaFuncSetAttribute(gemm_pipe32<3, 0>,
                             cudaFuncAttributeMaxDynamicSharedMemorySize, GP32_SMEM);
        cudaFuncSetAttribute(gemm_pipe32<0, 0>,
                             cudaFuncAttributeMaxDynamicSharedMemorySize, GP32_SMEM);
        attr_done = true;
    }

    const dim3 gProj (DIM / 128, TOK / 32, 1);        // (2, 128) = 256 CTAs
    const dim3 gQKV  (DIM / 128, TOK / 64, 3);        // (2, 64, 3)
    const dim3 gWo   (DIM / 128, CTOK / 32, 1);       // (2, 64)
    const dim3 gFFN1 (FFN_DIM / 128, CTOK / 64, 1);   // (8, 32)
    const dim3 gFFN2 (DIM / 128, CTOK / 32, 1);       // (2, 64)
    const dim3 gKV   (DIM / 128, CTOK / 32, 2);       // (2, 64, 2)

    // 0. Zero attention accumulator
    cudaMemsetAsync(accb, 0, (size_t)TOK * DIM * sizeof(float));

    // 1. Projection (+bias +posenc), gathered feats, K=512, BM=32 pipe
    gemm_pipe32<5, 1><<<gProj, 128, GP32_SMEM>>>(
        nullptr, W_proj, nullptr, b_proj, nullptr,
        x, nullptr, DIM, INDIM,
        target_feat, context_feats, target_pos, context_pos);

    // 2. LN1 (full)
    ln_kernel<<<(TOK * 32) / 256, 256>>>(x, ln1_s, ln1_b, h, TOK, DIM);

    // 3. QKV fused (full)
    gemm_pipe<0><<<gQKV, 256, GP_SMEM>>>(
        h, Wq, Wk, Wv, nullptr, q, k, v, DIM, DIM);

    // 4. Attention (atomic-add into accb)
    attn_all_kernel<<<896, 128>>>(q, k, v, accb);

    // 5. Wo + residual, compact: A=acc (cmap), res=x (cmap) -> x1c (g_q)
    gemm_pipe32<6, 2><<<gWo, 128, GP32_SMEM>>>(
        accb, Wo, nullptr, nullptr, x, q, nullptr, DIM, DIM,
        nullptr, nullptr, nullptr, nullptr);

    // 6. LN2 compact: g_q -> g_h
    ln_kernel<<<(CTOK * 32) / 256, 256>>>(q, ln2_s, ln2_b, h, CTOK, DIM);

    // 7. FFN1 compact: ffn = gelu(h @ W1 + b1)
    gemm_pipe<2><<<gFFN1, 256, GP_SMEM>>>(
        h, W1, nullptr, nullptr, b1, ffn, nullptr, nullptr, FFN_DIM, DIM);

    // 8. FFN2 compact: x2c = ffn @ W2 + b2 + x1c -> g_x  (K=1024)
    gemm_pipe32<3, 0><<<gFFN2, 128, GP32_SMEM>>>(
        ffn, W2, nullptr, b2, q, x, nullptr, DIM, FFN_DIM,
        nullptr, nullptr, nullptr, nullptr);

    // 9. LN1(l2) compact: g_x -> g_h
    ln_kernel<<<(CTOK * 32) / 256, 256>>>(x, ln1_s + DIM, ln1_b + DIM, h, CTOK, DIM);

    // 10. K,V compact (z=2)
    gemm_pipe32<0, 0><<<gKV, 128, GP32_SMEM>>>(
        h, Wk + DIM * DIM, Wv + DIM * DIM, nullptr, nullptr,
        k, v, DIM, DIM,
        nullptr, nullptr, nullptr, nullptr);

    // 11. Fused tail (compact inputs)
    tail_kernel<<<BATCH, 256>>>(
        x, h, k, v,
        Wq + DIM * DIM, Wo + DIM * DIM,
        W1 + DIM * FFN_DIM, W2 + FFN_DIM * DIM,
        b1 + FFN_DIM, b2 + DIM,
        ln2_s + DIM, ln2_b + DIM, lnf_s, lnf_b, out);
}